// round 1
// baseline (speedup 1.0000x reference)
#include <cuda_runtime.h>
#include <math.h>

#define BB 8
#define TT 2048
#define DD 1024
#define HH 128

// Scratch (static __device__ arrays: allocation-free per harness rules)
__device__ float g_Q[BB * TT * HH];                 // 8 MB
__device__ float g_K[BB * TT * HH];                 // 8 MB
__device__ float g_V[BB * TT * HH];                 // 8 MB
__device__ float g_E[(size_t)BB * TT * TT];         // 128 MB (exp(S), 0 below diag)
__device__ float g_d[BB * TT];                      // column sums

// ----------------------------------------------------------------------------
// Kernel 1: Out[M,N] = A[M,K] @ W[K,N] + bias[N]   (64x64 tile, 16x16 threads, 4x4/thread)
// ----------------------------------------------------------------------------
__global__ void sgemm_bias64(const float* __restrict__ A, const float* __restrict__ W,
                             const float* __restrict__ bias, float* __restrict__ Out,
                             int M, int N, int K) {
    __shared__ float As[16][64];
    __shared__ float Bs[16][64];
    const int tx = threadIdx.x, ty = threadIdx.y;
    const int tid = ty * 16 + tx;
    const int m0 = blockIdx.y * 64, n0 = blockIdx.x * 64;
    const int aRow = tid >> 2, aC = (tid & 3) * 4;   // 64 rows x 16 cols
    const int bRow = tid >> 4, bC = (tid & 15) * 4;  // 16 rows x 64 cols

    float acc[4][4] = {};
    for (int k0 = 0; k0 < K; k0 += 16) {
        float4 av = *(const float4*)&A[(size_t)(m0 + aRow) * K + k0 + aC];
        As[aC + 0][aRow] = av.x; As[aC + 1][aRow] = av.y;
        As[aC + 2][aRow] = av.z; As[aC + 3][aRow] = av.w;
        *(float4*)&Bs[bRow][bC] = *(const float4*)&W[(size_t)(k0 + bRow) * N + n0 + bC];
        __syncthreads();
#pragma unroll
        for (int kk = 0; kk < 16; kk++) {
            float4 a = *(const float4*)&As[kk][ty * 4];
            float4 b = *(const float4*)&Bs[kk][tx * 4];
            float ar[4] = {a.x, a.y, a.z, a.w};
            float br[4] = {b.x, b.y, b.z, b.w};
#pragma unroll
            for (int i = 0; i < 4; i++)
#pragma unroll
                for (int j = 0; j < 4; j++) acc[i][j] += ar[i] * br[j];
        }
        __syncthreads();
    }
#pragma unroll
    for (int i = 0; i < 4; i++) {
        const int m = m0 + ty * 4 + i;
        float4 bv = *(const float4*)&bias[n0 + tx * 4];
        float4 o = make_float4(acc[i][0] + bv.x, acc[i][1] + bv.y,
                               acc[i][2] + bv.z, acc[i][3] + bv.w);
        *(float4*)&Out[(size_t)m * N + n0 + tx * 4] = o;
    }
}

// ----------------------------------------------------------------------------
// Kernel 2: E = exp(Q @ K^T) on tiles with kTile >= qTile; E=0 where q>k.
// Also accumulates column sums d[k] = sum_{q<=k} E[q,k].
// ----------------------------------------------------------------------------
__global__ void attn_scores_kernel() {
    const int kT = blockIdx.x, qT = blockIdx.y, b = blockIdx.z;
    if (kT < qT) return;  // tile entirely masked
    const int q0 = qT * 64, k0 = kT * 64;

    __shared__ float Qs[16][64];
    __shared__ float Ks[16][64];
    __shared__ float red[16][64];

    const int tx = threadIdx.x, ty = threadIdx.y;
    const int tid = ty * 16 + tx;
    const int row = tid >> 2, c4 = (tid & 3) * 4;

    const float* Qb = g_Q + (size_t)b * TT * HH;
    const float* Kb = g_K + (size_t)b * TT * HH;

    float acc[4][4] = {};
    for (int h0 = 0; h0 < HH; h0 += 16) {
        float4 qv = *(const float4*)&Qb[(size_t)(q0 + row) * HH + h0 + c4];
        Qs[c4 + 0][row] = qv.x; Qs[c4 + 1][row] = qv.y;
        Qs[c4 + 2][row] = qv.z; Qs[c4 + 3][row] = qv.w;
        float4 kv = *(const float4*)&Kb[(size_t)(k0 + row) * HH + h0 + c4];
        Ks[c4 + 0][row] = kv.x; Ks[c4 + 1][row] = kv.y;
        Ks[c4 + 2][row] = kv.z; Ks[c4 + 3][row] = kv.w;
        __syncthreads();
#pragma unroll
        for (int kk = 0; kk < 16; kk++) {
            float4 a = *(const float4*)&Qs[kk][ty * 4];
            float4 c = *(const float4*)&Ks[kk][tx * 4];
            float ar[4] = {a.x, a.y, a.z, a.w};
            float br[4] = {c.x, c.y, c.z, c.w};
#pragma unroll
            for (int i = 0; i < 4; i++)
#pragma unroll
                for (int j = 0; j < 4; j++) acc[i][j] += ar[i] * br[j];
        }
        __syncthreads();
    }

    float* Eb = g_E + (size_t)b * TT * TT;
    float csum[4] = {0.f, 0.f, 0.f, 0.f};
#pragma unroll
    for (int i = 0; i < 4; i++) {
        const int q = q0 + ty * 4 + i;
        float vals[4];
#pragma unroll
        for (int j = 0; j < 4; j++) {
            const int k = k0 + tx * 4 + j;
            float e = (q <= k) ? __expf(acc[i][j]) : 0.f;
            vals[j] = e;
            csum[j] += e;
        }
        *(float4*)&Eb[(size_t)q * TT + k0 + tx * 4] =
            make_float4(vals[0], vals[1], vals[2], vals[3]);
    }
    // reduce partial column sums over ty, one atomicAdd per column
#pragma unroll
    for (int j = 0; j < 4; j++) red[ty][tx * 4 + j] = csum[j];
    __syncthreads();
    if (tid < 64) {
        float s = 0.f;
#pragma unroll
        for (int r = 0; r < 16; r++) s += red[r][tid];
        atomicAdd(&g_d[b * TT + k0 + tid], s);
    }
}

// ----------------------------------------------------------------------------
// Kernel 3: out[q,:] += E[q, k0:T] @ (V[k]/d[k]) over this block's k-split.
// Grid: (NSPLIT, T/64, B). Output is zeroed beforehand; partials via atomicAdd.
// ----------------------------------------------------------------------------
#define NSPLIT 4
__global__ void attn_out_kernel(float* __restrict__ Out) {
    const int seg = blockIdx.x, qT = blockIdx.y, b = blockIdx.z;
    const int q0 = qT * 64;
    const int ktFirst = q0 / 16;     // first 16-wide k tile (E==0 for k<q0)
    const int ktCount = TT / 16 - ktFirst;
    if (seg >= ktCount) return;

    __shared__ float Es[16][64];
    __shared__ float Vs[16][128];

    const int tx = threadIdx.x, ty = threadIdx.y;
    const int tid = ty * 16 + tx;
    const int eRow = tid >> 2, eC = (tid & 3) * 4;   // 64 x 16
    const int vRow = tid >> 4, vC = (tid & 15) * 8;  // 16 x 128

    const float* Eb = g_E + (size_t)b * TT * TT;
    const float* Vb = g_V + (size_t)b * TT * HH;
    const float* db = g_d + b * TT;

    float acc[4][8] = {};
    for (int kt = ktFirst + seg; kt < TT / 16; kt += NSPLIT) {
        const int k0 = kt * 16;
        float4 ev = *(const float4*)&Eb[(size_t)(q0 + eRow) * TT + k0 + eC];
        Es[eC + 0][eRow] = ev.x; Es[eC + 1][eRow] = ev.y;
        Es[eC + 2][eRow] = ev.z; Es[eC + 3][eRow] = ev.w;
        const float inv = 1.0f / db[k0 + vRow];
        float4 v0 = *(const float4*)&Vb[(size_t)(k0 + vRow) * HH + vC];
        float4 v1 = *(const float4*)&Vb[(size_t)(k0 + vRow) * HH + vC + 4];
        v0.x *= inv; v0.y *= inv; v0.z *= inv; v0.w *= inv;
        v1.x *= inv; v1.y *= inv; v1.z *= inv; v1.w *= inv;
        *(float4*)&Vs[vRow][vC] = v0;
        *(float4*)&Vs[vRow][vC + 4] = v1;
        __syncthreads();
#pragma unroll
        for (int kk = 0; kk < 16; kk++) {
            float4 a = *(const float4*)&Es[kk][ty * 4];
            float ar[4] = {a.x, a.y, a.z, a.w};
            float4 b0 = *(const float4*)&Vs[kk][tx * 8];
            float4 b1 = *(const float4*)&Vs[kk][tx * 8 + 4];
            float br[8] = {b0.x, b0.y, b0.z, b0.w, b1.x, b1.y, b1.z, b1.w};
#pragma unroll
            for (int i = 0; i < 4; i++)
#pragma unroll
                for (int j = 0; j < 8; j++) acc[i][j] += ar[i] * br[j];
        }
        __syncthreads();
    }
#pragma unroll
    for (int i = 0; i < 4; i++) {
        const int q = q0 + ty * 4 + i;
        float* op = Out + ((size_t)(b * TT + q)) * HH + tx * 8;
#pragma unroll
        for (int j = 0; j < 8; j++) atomicAdd(&op[j], acc[i][j]);
    }
}

// ----------------------------------------------------------------------------
extern "C" void kernel_launch(void* const* d_in, const int* in_sizes, int n_in,
                              void* d_out, int out_size) {
    const float* x  = (const float*)d_in[0];
    const float* Wq = (const float*)d_in[1];
    const float* bq = (const float*)d_in[2];
    const float* Wk = (const float*)d_in[3];
    const float* bk = (const float*)d_in[4];
    const float* Wv = (const float*)d_in[5];
    const float* bv = (const float*)d_in[6];
    float* out = (float*)d_out;

    float *pQ, *pK, *pV, *pd;
    cudaGetSymbolAddress((void**)&pQ, g_Q);
    cudaGetSymbolAddress((void**)&pK, g_K);
    cudaGetSymbolAddress((void**)&pV, g_V);
    cudaGetSymbolAddress((void**)&pd, g_d);

    cudaMemsetAsync(pd, 0, BB * TT * sizeof(float));
    cudaMemsetAsync(out, 0, (size_t)out_size * sizeof(float));

    dim3 blk(16, 16);
    dim3 gProj(HH / 64, (BB * TT) / 64);
    sgemm_bias64<<<gProj, blk>>>(x, Wq, bq, pQ, BB * TT, HH, DD);
    sgemm_bias64<<<gProj, blk>>>(x, Wk, bk, pK, BB * TT, HH, DD);
    sgemm_bias64<<<gProj, blk>>>(x, Wv, bv, pV, BB * TT, HH, DD);

    attn_scores_kernel<<<dim3(TT / 64, TT / 64, BB), blk>>>();
    attn_out_kernel<<<dim3(NSPLIT, TT / 64, BB), blk>>>(out);
}

// round 2
// speedup vs baseline: 1.0037x; 1.0037x over previous
#include <cuda_runtime.h>
#include <math.h>

#define BB 8
#define TT 2048
#define DD 1024
#define HH 128

// Scratch (static __device__ arrays: allocation-free per harness rules)
__device__ float g_Q[BB * TT * HH];                 // 8 MB
__device__ float g_K[BB * TT * HH];                 // 8 MB
__device__ float g_V[BB * TT * HH];                 // 8 MB
__device__ float g_E[(size_t)BB * TT * TT];         // 128 MB (exp(S), 0 below diag)
__device__ float g_d[BB * TT];                      // column sums

// ----------------------------------------------------------------------------
// Kernel 1: Out[M,N] = A[M,K] @ W[K,N] + bias[N]   (64x64 tile, 16x16 threads, 4x4/thread)
// ----------------------------------------------------------------------------
__global__ void sgemm_bias64(const float* __restrict__ A, const float* __restrict__ W,
                             const float* __restrict__ bias, float* __restrict__ Out,
                             int M, int N, int K) {
    __shared__ float As[16][64];
    __shared__ float Bs[16][64];
    const int tx = threadIdx.x, ty = threadIdx.y;
    const int tid = ty * 16 + tx;
    const int m0 = blockIdx.y * 64, n0 = blockIdx.x * 64;
    const int aRow = tid >> 2, aC = (tid & 3) * 4;   // 64 rows x 16 cols
    const int bRow = tid >> 4, bC = (tid & 15) * 4;  // 16 rows x 64 cols

    float acc[4][4] = {};
    for (int k0 = 0; k0 < K; k0 += 16) {
        float4 av = *(const float4*)&A[(size_t)(m0 + aRow) * K + k0 + aC];
        As[aC + 0][aRow] = av.x; As[aC + 1][aRow] = av.y;
        As[aC + 2][aRow] = av.z; As[aC + 3][aRow] = av.w;
        *(float4*)&Bs[bRow][bC] = *(const float4*)&W[(size_t)(k0 + bRow) * N + n0 + bC];
        __syncthreads();
#pragma unroll
        for (int kk = 0; kk < 16; kk++) {
            float4 a = *(const float4*)&As[kk][ty * 4];
            float4 b = *(const float4*)&Bs[kk][tx * 4];
            float ar[4] = {a.x, a.y, a.z, a.w};
            float br[4] = {b.x, b.y, b.z, b.w};
#pragma unroll
            for (int i = 0; i < 4; i++)
#pragma unroll
                for (int j = 0; j < 4; j++) acc[i][j] += ar[i] * br[j];
        }
        __syncthreads();
    }
#pragma unroll
    for (int i = 0; i < 4; i++) {
        const int m = m0 + ty * 4 + i;
        float4 bv = *(const float4*)&bias[n0 + tx * 4];
        float4 o = make_float4(acc[i][0] + bv.x, acc[i][1] + bv.y,
                               acc[i][2] + bv.z, acc[i][3] + bv.w);
        *(float4*)&Out[(size_t)m * N + n0 + tx * 4] = o;
    }
}

// ----------------------------------------------------------------------------
// Kernel 2: E = exp(Q @ K^T) on tiles with kTile >= qTile; E=0 where q>k.
// Also accumulates column sums d[k] = sum_{q<=k} E[q,k].
// ----------------------------------------------------------------------------
__global__ void attn_scores_kernel() {
    const int kT = blockIdx.x, qT = blockIdx.y, b = blockIdx.z;
    if (kT < qT) return;  // tile entirely masked
    const int q0 = qT * 64, k0 = kT * 64;

    __shared__ float Qs[16][64];
    __shared__ float Ks[16][64];
    __shared__ float red[16][64];

    const int tx = threadIdx.x, ty = threadIdx.y;
    const int tid = ty * 16 + tx;
    const int row = tid >> 2, c4 = (tid & 3) * 4;

    const float* Qb = g_Q + (size_t)b * TT * HH;
    const float* Kb = g_K + (size_t)b * TT * HH;

    float acc[4][4] = {};
    for (int h0 = 0; h0 < HH; h0 += 16) {
        float4 qv = *(const float4*)&Qb[(size_t)(q0 + row) * HH + h0 + c4];
        Qs[c4 + 0][row] = qv.x; Qs[c4 + 1][row] = qv.y;
        Qs[c4 + 2][row] = qv.z; Qs[c4 + 3][row] = qv.w;
        float4 kv = *(const float4*)&Kb[(size_t)(k0 + row) * HH + h0 + c4];
        Ks[c4 + 0][row] = kv.x; Ks[c4 + 1][row] = kv.y;
        Ks[c4 + 2][row] = kv.z; Ks[c4 + 3][row] = kv.w;
        __syncthreads();
#pragma unroll
        for (int kk = 0; kk < 16; kk++) {
            float4 a = *(const float4*)&Qs[kk][ty * 4];
            float4 c = *(const float4*)&Ks[kk][tx * 4];
            float ar[4] = {a.x, a.y, a.z, a.w};
            float br[4] = {c.x, c.y, c.z, c.w};
#pragma unroll
            for (int i = 0; i < 4; i++)
#pragma unroll
                for (int j = 0; j < 4; j++) acc[i][j] += ar[i] * br[j];
        }
        __syncthreads();
    }

    float* Eb = g_E + (size_t)b * TT * TT;
    float csum[4] = {0.f, 0.f, 0.f, 0.f};
#pragma unroll
    for (int i = 0; i < 4; i++) {
        const int q = q0 + ty * 4 + i;
        float vals[4];
#pragma unroll
        for (int j = 0; j < 4; j++) {
            const int k = k0 + tx * 4 + j;
            float e = (q <= k) ? __expf(acc[i][j]) : 0.f;
            vals[j] = e;
            csum[j] += e;
        }
        *(float4*)&Eb[(size_t)q * TT + k0 + tx * 4] =
            make_float4(vals[0], vals[1], vals[2], vals[3]);
    }
    // reduce partial column sums over ty, one atomicAdd per column
#pragma unroll
    for (int j = 0; j < 4; j++) red[ty][tx * 4 + j] = csum[j];
    __syncthreads();
    if (tid < 64) {
        float s = 0.f;
#pragma unroll
        for (int r = 0; r < 16; r++) s += red[r][tid];
        atomicAdd(&g_d[b * TT + k0 + tid], s);
    }
}

// ----------------------------------------------------------------------------
// Kernel 3: out[q,:] += E[q, k0:T] @ (V[k]/d[k]) over this block's k-split.
// Grid: (NSPLIT, T/64, B). Output is zeroed beforehand; partials via atomicAdd.
// ----------------------------------------------------------------------------
#define NSPLIT 4
__global__ void attn_out_kernel(float* __restrict__ Out) {
    const int seg = blockIdx.x, qT = blockIdx.y, b = blockIdx.z;
    const int q0 = qT * 64;
    const int ktFirst = q0 / 16;     // first 16-wide k tile (E==0 for k<q0)
    const int ktCount = TT / 16 - ktFirst;
    if (seg >= ktCount) return;

    __shared__ float Es[16][64];
    __shared__ float Vs[16][128];

    const int tx = threadIdx.x, ty = threadIdx.y;
    const int tid = ty * 16 + tx;
    const int eRow = tid >> 2, eC = (tid & 3) * 4;   // 64 x 16
    const int vRow = tid >> 4, vC = (tid & 15) * 8;  // 16 x 128

    const float* Eb = g_E + (size_t)b * TT * TT;
    const float* Vb = g_V + (size_t)b * TT * HH;
    const float* db = g_d + b * TT;

    float acc[4][8] = {};
    for (int kt = ktFirst + seg; kt < TT / 16; kt += NSPLIT) {
        const int k0 = kt * 16;
        float4 ev = *(const float4*)&Eb[(size_t)(q0 + eRow) * TT + k0 + eC];
        Es[eC + 0][eRow] = ev.x; Es[eC + 1][eRow] = ev.y;
        Es[eC + 2][eRow] = ev.z; Es[eC + 3][eRow] = ev.w;
        const float inv = 1.0f / db[k0 + vRow];
        float4 v0 = *(const float4*)&Vb[(size_t)(k0 + vRow) * HH + vC];
        float4 v1 = *(const float4*)&Vb[(size_t)(k0 + vRow) * HH + vC + 4];
        v0.x *= inv; v0.y *= inv; v0.z *= inv; v0.w *= inv;
        v1.x *= inv; v1.y *= inv; v1.z *= inv; v1.w *= inv;
        *(float4*)&Vs[vRow][vC] = v0;
        *(float4*)&Vs[vRow][vC + 4] = v1;
        __syncthreads();
#pragma unroll
        for (int kk = 0; kk < 16; kk++) {
            float4 a = *(const float4*)&Es[kk][ty * 4];
            float ar[4] = {a.x, a.y, a.z, a.w};
            float4 b0 = *(const float4*)&Vs[kk][tx * 8];
            float4 b1 = *(const float4*)&Vs[kk][tx * 8 + 4];
            float br[8] = {b0.x, b0.y, b0.z, b0.w, b1.x, b1.y, b1.z, b1.w};
#pragma unroll
            for (int i = 0; i < 4; i++)
#pragma unroll
                for (int j = 0; j < 8; j++) acc[i][j] += ar[i] * br[j];
        }
        __syncthreads();
    }
#pragma unroll
    for (int i = 0; i < 4; i++) {
        const int q = q0 + ty * 4 + i;
        float* op = Out + ((size_t)(b * TT + q)) * HH + tx * 8;
#pragma unroll
        for (int j = 0; j < 8; j++) atomicAdd(&op[j], acc[i][j]);
    }
}

// ----------------------------------------------------------------------------
extern "C" void kernel_launch(void* const* d_in, const int* in_sizes, int n_in,
                              void* d_out, int out_size) {
    const float* x  = (const float*)d_in[0];
    const float* Wq = (const float*)d_in[1];
    const float* bq = (const float*)d_in[2];
    const float* Wk = (const float*)d_in[3];
    const float* bk = (const float*)d_in[4];
    const float* Wv = (const float*)d_in[5];
    const float* bv = (const float*)d_in[6];
    float* out = (float*)d_out;

    float *pQ, *pK, *pV, *pd;
    cudaGetSymbolAddress((void**)&pQ, g_Q);
    cudaGetSymbolAddress((void**)&pK, g_K);
    cudaGetSymbolAddress((void**)&pV, g_V);
    cudaGetSymbolAddress((void**)&pd, g_d);

    cudaMemsetAsync(pd, 0, BB * TT * sizeof(float));
    cudaMemsetAsync(out, 0, (size_t)out_size * sizeof(float));

    dim3 blk(16, 16);
    dim3 gProj(HH / 64, (BB * TT) / 64);
    sgemm_bias64<<<gProj, blk>>>(x, Wq, bq, pQ, BB * TT, HH, DD);
    sgemm_bias64<<<gProj, blk>>>(x, Wk, bk, pK, BB * TT, HH, DD);
    sgemm_bias64<<<gProj, blk>>>(x, Wv, bv, pV, BB * TT, HH, DD);

    attn_scores_kernel<<<dim3(TT / 64, TT / 64, BB), blk>>>();
    attn_out_kernel<<<dim3(NSPLIT, TT / 64, BB), blk>>>(out);
}

// round 5
// speedup vs baseline: 2.6117x; 2.6022x over previous
#include <cuda_runtime.h>
#include <cuda_bf16.h>
#include <cstdint>

#define BB 8
#define TT 2048
#define DD 1024
#define HH 128
#define SMEM_BYTES 81920
#define STG 40960

// ---- static scratch (allocation-free) ----
__device__ __nv_bfloat16 g_xh[BB * TT * DD], g_xl[BB * TT * DD];     // x hi/lo
__device__ __nv_bfloat16 g_Wh[DD * 384], g_Wl[DD * 384];             // [k][w*128+n]
__device__ float g_bias[384];
__device__ __nv_bfloat16 g_Qh[BB * TT * HH], g_Ql[BB * TT * HH];
__device__ __nv_bfloat16 g_Kh[BB * TT * HH], g_Kl[BB * TT * HH];
__device__ float g_V[BB * TT * HH];
__device__ __nv_bfloat16 g_Eh[(size_t)BB * TT * TT], g_El[(size_t)BB * TT * TT];
__device__ __nv_bfloat16 g_Vdh[BB * TT * HH], g_Vdl[BB * TT * HH];   // (V/d) [k][n]
__device__ float g_d[BB * TT];

// ---- helpers ----
__device__ __forceinline__ void bsplit(float x, __nv_bfloat16& h, __nv_bfloat16& l) {
    h = __float2bfloat16(x);
    l = __float2bfloat16(x - __bfloat162float(h));
}
__device__ __forceinline__ uint32_t s2u(const void* p) {
    uint32_t a;
    asm("{ .reg .u64 t; cvta.to.shared.u64 t, %1; cvt.u32.u64 %0, t; }" : "=r"(a) : "l"(p));
    return a;
}
__device__ __forceinline__ void cpa16(uint32_t dst, const void* src) {
    asm volatile("cp.async.cg.shared.global [%0], [%1], 16;" :: "r"(dst), "l"(src));
}
__device__ __forceinline__ void cp_commit() { asm volatile("cp.async.commit_group;"); }
__device__ __forceinline__ void cp_wait1() { asm volatile("cp.async.wait_group 1;"); }
__device__ __forceinline__ void cp_wait0() { asm volatile("cp.async.wait_group 0;"); }
__device__ __forceinline__ void ldm_x4(uint32_t* r, uint32_t a) {
    asm volatile("ldmatrix.sync.aligned.m8n8.x4.shared.b16 {%0,%1,%2,%3},[%4];"
                 : "=r"(r[0]), "=r"(r[1]), "=r"(r[2]), "=r"(r[3]) : "r"(a));
}
__device__ __forceinline__ void ldm_x2(uint32_t* r, uint32_t a) {
    asm volatile("ldmatrix.sync.aligned.m8n8.x2.shared.b16 {%0,%1},[%2];"
                 : "=r"(r[0]), "=r"(r[1]) : "r"(a));
}
__device__ __forceinline__ void ldm_x2t(uint32_t* r, uint32_t a) {
    asm volatile("ldmatrix.sync.aligned.m8n8.x2.trans.shared.b16 {%0,%1},[%2];"
                 : "=r"(r[0]), "=r"(r[1]) : "r"(a));
}
__device__ __forceinline__ void mmabf(float* c, const uint32_t* a, const uint32_t* b) {
    asm volatile(
        "mma.sync.aligned.m16n8k16.row.col.f32.bf16.bf16.f32 "
        "{%0,%1,%2,%3},{%4,%5,%6,%7},{%8,%9},{%0,%1,%2,%3};"
        : "+f"(c[0]), "+f"(c[1]), "+f"(c[2]), "+f"(c[3])
        : "r"(a[0]), "r"(a[1]), "r"(a[2]), "r"(a[3]), "r"(b[0]), "r"(b[1]));
}

// load one 32-k chunk into stage buffer (A: [128m][32k]; B: trans? [32k][128n] : [128n][32k])
template <bool BT>
__device__ __forceinline__ void ld_chunk(const __nv_bfloat16* Ah, const __nv_bfloat16* Al, int lda,
                                         const __nv_bfloat16* Bh, const __nv_bfloat16* Bl, int ldb,
                                         uint32_t sb, int tid) {
    {
        int r = tid >> 2, seg = tid & 3;
        size_t so = (size_t)r * lda + seg * 8;
        uint32_t d = sb + r * 80 + seg * 16;
        cpa16(d, Ah + so);
        cpa16(d + 10240, Al + so);
    }
    if (!BT) {
        int r = tid >> 2, seg = tid & 3;
        size_t so = (size_t)r * ldb + seg * 8;
        uint32_t d = sb + 20480 + r * 80 + seg * 16;
        cpa16(d, Bh + so);
        cpa16(d + 10240, Bl + so);
    } else {
        int r = tid >> 4, seg = tid & 15;
        size_t so = (size_t)r * ldb + seg * 8;
        uint32_t d = sb + 20480 + r * 272 + seg * 16;
        cpa16(d, Bh + so);
        cpa16(d + 10240, Bl + so);
    }
}

template <bool BT>
__device__ __forceinline__ void compute_chunk(uint32_t sb, float acc[2][4][4],
                                              int lane, int wm, int wn) {
#pragma unroll
    for (int ks = 0; ks < 2; ks++) {
        uint32_t ah[2][4], al[2][4];
#pragma unroll
        for (int mt = 0; mt < 2; mt++) {
            uint32_t ad = sb + (wm * 32 + mt * 16 + (lane & 15)) * 80 + ks * 32 + (lane >> 4) * 16;
            ldm_x4(ah[mt], ad);
            ldm_x4(al[mt], ad + 10240);
        }
        uint32_t bh[4][2], bl[4][2];
#pragma unroll
        for (int nt = 0; nt < 4; nt++) {
            if (!BT) {
                uint32_t bd = sb + 20480 + (wn * 32 + nt * 8 + (lane & 7)) * 80 + ks * 32 +
                              ((lane >> 3) & 1) * 16;
                ldm_x2(bh[nt], bd);
                ldm_x2(bl[nt], bd + 10240);
            } else {
                uint32_t bd = sb + 20480 + (ks * 16 + (lane & 15)) * 272 + (wn * 32 + nt * 8) * 2;
                ldm_x2t(bh[nt], bd);
                ldm_x2t(bl[nt], bd + 10240);
            }
        }
#pragma unroll
        for (int mt = 0; mt < 2; mt++)
#pragma unroll
            for (int nt = 0; nt < 4; nt++) {
                mmabf(acc[mt][nt], ah[mt], bh[nt]);
                mmabf(acc[mt][nt], ah[mt], bl[nt]);
                mmabf(acc[mt][nt], al[mt], bh[nt]);
            }
    }
}

// full pipelined GEMM over n chunks; per-chunk operand advance in elements
template <bool BT>
__device__ __forceinline__ void gemm_pipe(const __nv_bfloat16* Ah, const __nv_bfloat16* Al, int lda,
                                          const __nv_bfloat16* Bh, const __nv_bfloat16* Bl, int ldb,
                                          int n, size_t aStep, size_t bStep,
                                          uint32_t sb, float acc[2][4][4], int tid) {
    const int lane = tid & 31, wid = tid >> 5;
    const int wm = wid >> 2, wn = wid & 3;
    ld_chunk<BT>(Ah, Al, lda, Bh, Bl, ldb, sb, tid);
    cp_commit();
    for (int i = 0; i < n; i++) {
        if (i + 1 < n) {
            ld_chunk<BT>(Ah + (i + 1) * aStep, Al + (i + 1) * aStep, lda,
                         Bh + (i + 1) * bStep, Bl + (i + 1) * bStep, ldb,
                         sb + ((i + 1) & 1) * STG, tid);
            cp_commit();
            cp_wait1();
        } else {
            cp_wait0();
        }
        __syncthreads();
        compute_chunk<BT>(sb + (i & 1) * STG, acc, lane, wm, wn);
        __syncthreads();
    }
}

// ---- convert kernels ----
__global__ void convx_kernel(const float* __restrict__ x) {
    size_t i = ((size_t)blockIdx.x * 256 + threadIdx.x) * 4;
    float4 v = *(const float4*)&x[i];
    __nv_bfloat16 h0, l0, h1, l1, h2, l2, h3, l3;
    bsplit(v.x, h0, l0); bsplit(v.y, h1, l1);
    bsplit(v.z, h2, l2); bsplit(v.w, h3, l3);
    *(__nv_bfloat162*)&g_xh[i] = {h0, h1};
    *(__nv_bfloat162*)&g_xh[i + 2] = {h2, h3};
    *(__nv_bfloat162*)&g_xl[i] = {l0, l1};
    *(__nv_bfloat162*)&g_xl[i + 2] = {l2, l3};
}
__global__ void convw_kernel(const float* __restrict__ Wq, const float* __restrict__ Wk,
                             const float* __restrict__ Wv, const float* __restrict__ bq,
                             const float* __restrict__ bk, const float* __restrict__ bv) {
    int i = blockIdx.x * 256 + threadIdx.x;            // over 3*1024*128
    int w = i / (DD * HH), rem = i % (DD * HH);
    int r = rem / HH, c = rem % HH;
    const float* W = (w == 0) ? Wq : (w == 1) ? Wk : Wv;
    float v = W[(size_t)r * HH + c];
    __nv_bfloat16 h, l;
    bsplit(v, h, l);
    g_Wh[(size_t)r * 384 + w * 128 + c] = h;
    g_Wl[(size_t)r * 384 + w * 128 + c] = l;
    if (i < 384)   // FIX: was gated on blockIdx.x==0, leaving bias[256..383] unset
        g_bias[i] = (i < 128) ? bq[i] : (i < 256) ? bk[i - 128] : bv[i - 256];
}
__global__ void convvd_kernel() {
    int b = blockIdx.y;
    size_t i = (size_t)blockIdx.x * 256 + threadIdx.x;  // over TT*HH
    int k = (int)(i / HH);
    float inv = 1.0f / g_d[b * TT + k];
    size_t gi = (size_t)b * TT * HH + i;
    float v = g_V[gi] * inv;
    __nv_bfloat16 h, l;
    bsplit(v, h, l);
    g_Vdh[gi] = h;
    g_Vdl[gi] = l;
}

// ---- stage 1: projections (N blocks: 0=Q, 1=K, 2=V) ----
__global__ void __launch_bounds__(512, 1) proj_kernel() {
    extern __shared__ char sm[];
    const uint32_t sb = s2u(sm);
    const int tid = threadIdx.x, lane = tid & 31, wid = tid >> 5;
    const int wm = wid >> 2, wn = wid & 3;
    const int w = blockIdx.x, m0 = blockIdx.y * 128;
    float acc[2][4][4] = {};
    gemm_pipe<true>(g_xh + (size_t)m0 * DD, g_xl + (size_t)m0 * DD, DD,
                    g_Wh + w * 128, g_Wl + w * 128, 384,
                    32, 32, (size_t)32 * 384, sb, acc, tid);
    const float* bias = g_bias + w * 128;
#pragma unroll
    for (int mt = 0; mt < 2; mt++)
#pragma unroll
        for (int nt = 0; nt < 4; nt++)
#pragma unroll
            for (int h = 0; h < 2; h++) {
                int row = wm * 32 + mt * 16 + (lane >> 2) + h * 8;
                int col = wn * 32 + nt * 8 + (lane & 3) * 2;
                size_t gm = (size_t)(m0 + row);
                float v0 = acc[mt][nt][h * 2] + bias[col];
                float v1 = acc[mt][nt][h * 2 + 1] + bias[col + 1];
                if (w == 2) {
                    *(float2*)&g_V[gm * HH + col] = make_float2(v0, v1);
                } else {
                    __nv_bfloat16 h0, l0, h1, l1;
                    bsplit(v0, h0, l0); bsplit(v1, h1, l1);
                    __nv_bfloat162 hh = {h0, h1}, ll = {l0, l1};
                    if (w == 0) {
                        *(__nv_bfloat162*)&g_Qh[gm * HH + col] = hh;
                        *(__nv_bfloat162*)&g_Ql[gm * HH + col] = ll;
                    } else {
                        *(__nv_bfloat162*)&g_Kh[gm * HH + col] = hh;
                        *(__nv_bfloat162*)&g_Kl[gm * HH + col] = ll;
                    }
                }
            }
}

// ---- stage 2: scores E=exp(QK^T) upper-tri tiles, col sums ----
__global__ void __launch_bounds__(512, 1) scores_kernel() {
    const int kT = blockIdx.x, qT = blockIdx.y, b = blockIdx.z;
    if (kT < qT) return;
    extern __shared__ char sm[];
    const uint32_t sb = s2u(sm);
    const int tid = threadIdx.x, lane = tid & 31, wid = tid >> 5;
    const int wm = wid >> 2, wn = wid & 3;
    const int q0 = qT * 128, k0 = kT * 128;
    const size_t mq = (size_t)b * TT + q0, mk = (size_t)b * TT + k0;
    float acc[2][4][4] = {};
    gemm_pipe<false>(g_Qh + mq * HH, g_Ql + mq * HH, HH,
                     g_Kh + mk * HH, g_Kl + mk * HH, HH,
                     4, 32, 32, sb, acc, tid);
    float* se = (float*)sm;  // [128][136]
#pragma unroll
    for (int mt = 0; mt < 2; mt++)
#pragma unroll
        for (int nt = 0; nt < 4; nt++)
#pragma unroll
            for (int h = 0; h < 2; h++) {
                int row = wm * 32 + mt * 16 + (lane >> 2) + h * 8;
                int col = wn * 32 + nt * 8 + (lane & 3) * 2;
                int q = q0 + row;
                float e0 = (q <= k0 + col) ? __expf(acc[mt][nt][h * 2]) : 0.f;
                float e1 = (q <= k0 + col + 1) ? __expf(acc[mt][nt][h * 2 + 1]) : 0.f;
                se[row * 136 + col] = e0;
                se[row * 136 + col + 1] = e1;
            }
    __syncthreads();
    if (tid < 128) {
        float s = 0.f;
#pragma unroll 8
        for (int r = 0; r < 128; r++) s += se[r * 136 + tid];
        atomicAdd(&g_d[b * TT + k0 + tid], s);
    }
    __nv_bfloat16* Eh = g_Eh + (size_t)b * TT * TT;
    __nv_bfloat16* El = g_El + (size_t)b * TT * TT;
#pragma unroll 4
    for (int i = 0; i < 16; i++) {
        int e = tid + i * 512;
        int q = e >> 6, kk = (e & 63) * 2;
        float v0 = se[q * 136 + kk], v1 = se[q * 136 + kk + 1];
        __nv_bfloat16 h0, l0, h1, l1;
        bsplit(v0, h0, l0); bsplit(v1, h1, l1);
        size_t o = (size_t)(q0 + q) * TT + k0 + kk;
        *(__nv_bfloat162*)&Eh[o] = {h0, h1};
        *(__nv_bfloat162*)&El[o] = {l0, l1};
    }
}

// ---- stage 3: out += E @ (V/d), 4-way split-k, atomics ----
__global__ void __launch_bounds__(512, 1) out_kernel(float* __restrict__ Out) {
    const int seg = blockIdx.x, qT = blockIdx.y, b = blockIdx.z;
    extern __shared__ char sm[];
    const uint32_t sb = s2u(sm);
    const int tid = threadIdx.x, lane = tid & 31, wid = tid >> 5;
    const int wm = wid >> 2, wn = wid & 3;
    const int q0 = qT * 128;
    const int c0 = q0 / 32 + seg;
    const int nch = (TT - q0) / 32;
    const int nIter = (nch - seg + 3) / 4;
    if (nIter <= 0) return;
    const __nv_bfloat16* Ah = g_Eh + ((size_t)b * TT + q0) * TT + (size_t)c0 * 32;
    const __nv_bfloat16* Al = g_El + ((size_t)b * TT + q0) * TT + (size_t)c0 * 32;
    const __nv_bfloat16* Bh = g_Vdh + (size_t)b * TT * HH + (size_t)c0 * 32 * HH;
    const __nv_bfloat16* Bl = g_Vdl + (size_t)b * TT * HH + (size_t)c0 * 32 * HH;
    float acc[2][4][4] = {};
    gemm_pipe<true>(Ah, Al, TT, Bh, Bl, HH, nIter, 128, (size_t)128 * HH, sb, acc, tid);
    float* ob = Out + ((size_t)b * TT + q0) * HH;
#pragma unroll
    for (int mt = 0; mt < 2; mt++)
#pragma unroll
        for (int nt = 0; nt < 4; nt++)
#pragma unroll
            for (int h = 0; h < 2; h++) {
                int row = wm * 32 + mt * 16 + (lane >> 2) + h * 8;
                int col = wn * 32 + nt * 8 + (lane & 3) * 2;
                atomicAdd(&ob[(size_t)row * HH + col], acc[mt][nt][h * 2]);
                atomicAdd(&ob[(size_t)row * HH + col + 1], acc[mt][nt][h * 2 + 1]);
            }
}

// ----------------------------------------------------------------------------
extern "C" void kernel_launch(void* const* d_in, const int* in_sizes, int n_in,
                              void* d_out, int out_size) {
    const float* x  = (const float*)d_in[0];
    const float* Wq = (const float*)d_in[1];
    const float* bq = (const float*)d_in[2];
    const float* Wk = (const float*)d_in[3];
    const float* bk = (const float*)d_in[4];
    const float* Wv = (const float*)d_in[5];
    const float* bv = (const float*)d_in[6];
    float* out = (float*)d_out;

    float* pd;
    cudaGetSymbolAddress((void**)&pd, g_d);
    cudaMemsetAsync(pd, 0, BB * TT * sizeof(float));
    cudaMemsetAsync(out, 0, (size_t)out_size * sizeof(float));

    cudaFuncSetAttribute(proj_kernel, cudaFuncAttributeMaxDynamicSharedMemorySize, SMEM_BYTES);
    cudaFuncSetAttribute(scores_kernel, cudaFuncAttributeMaxDynamicSharedMemorySize, SMEM_BYTES);
    cudaFuncSetAttribute(out_kernel, cudaFuncAttributeMaxDynamicSharedMemorySize, SMEM_BYTES);

    convx_kernel<<<BB * TT * DD / 1024, 256>>>(x);
    convw_kernel<<<3 * DD * HH / 256, 256>>>(Wq, Wk, Wv, bq, bk, bv);
    proj_kernel<<<dim3(3, BB * TT / 128), 512, SMEM_BYTES>>>();
    scores_kernel<<<dim3(16, 16, BB), 512, SMEM_BYTES>>>();
    convvd_kernel<<<dim3(TT * HH / 256, BB), 256>>>();
    out_kernel<<<dim3(4, 16, BB), 512, SMEM_BYTES>>>(out);
}

// round 6
// speedup vs baseline: 3.0404x; 1.1642x over previous
#include <cuda_runtime.h>
#include <cuda_bf16.h>
#include <cstdint>

#define BB 8
#define TT 2048
#define DD 1024
#define HH 128
#define SMEM_BYTES 81920
#define STG 40960

// ---- static scratch (allocation-free) ----
__device__ __nv_bfloat16 g_xh[BB * TT * DD], g_xl[BB * TT * DD];
__device__ __nv_bfloat16 g_Wh[DD * 384], g_Wl[DD * 384];             // [k][w*128+n]
__device__ float g_bias[384];
__device__ __nv_bfloat16 g_Qh[BB * TT * HH], g_Ql[BB * TT * HH];
__device__ __nv_bfloat16 g_Kh[BB * TT * HH], g_Kl[BB * TT * HH];
__device__ float g_V[BB * TT * HH];
__device__ __nv_bfloat16 g_Eh[(size_t)BB * TT * TT], g_El[(size_t)BB * TT * TT];
__device__ __nv_bfloat16 g_Vdh[BB * TT * HH], g_Vdl[BB * TT * HH];   // (V/d) [k][n]
__device__ float g_d[BB * TT];

// ---- helpers ----
__device__ __forceinline__ void bsplit(float x, __nv_bfloat16& h, __nv_bfloat16& l) {
    h = __float2bfloat16(x);
    l = __float2bfloat16(x - __bfloat162float(h));
}
__device__ __forceinline__ uint32_t s2u(const void* p) {
    uint32_t a;
    asm("{ .reg .u64 t; cvta.to.shared.u64 t, %1; cvt.u32.u64 %0, t; }" : "=r"(a) : "l"(p));
    return a;
}
__device__ __forceinline__ void cpa16(uint32_t dst, const void* src) {
    asm volatile("cp.async.cg.shared.global [%0], [%1], 16;" :: "r"(dst), "l"(src));
}
__device__ __forceinline__ void cp_commit() { asm volatile("cp.async.commit_group;"); }
__device__ __forceinline__ void cp_wait1() { asm volatile("cp.async.wait_group 1;"); }
__device__ __forceinline__ void cp_wait0() { asm volatile("cp.async.wait_group 0;"); }
__device__ __forceinline__ void ldm_x4(uint32_t* r, uint32_t a) {
    asm volatile("ldmatrix.sync.aligned.m8n8.x4.shared.b16 {%0,%1,%2,%3},[%4];"
                 : "=r"(r[0]), "=r"(r[1]), "=r"(r[2]), "=r"(r[3]) : "r"(a));
}
__device__ __forceinline__ void ldm_x4t(uint32_t* r, uint32_t a) {
    asm volatile("ldmatrix.sync.aligned.m8n8.x4.trans.shared.b16 {%0,%1,%2,%3},[%4];"
                 : "=r"(r[0]), "=r"(r[1]), "=r"(r[2]), "=r"(r[3]) : "r"(a));
}
__device__ __forceinline__ void mmabf(float* c, const uint32_t* a, const uint32_t* b) {
    asm volatile(
        "mma.sync.aligned.m16n8k16.row.col.f32.bf16.bf16.f32 "
        "{%0,%1,%2,%3},{%4,%5,%6,%7},{%8,%9},{%0,%1,%2,%3};"
        : "+f"(c[0]), "+f"(c[1]), "+f"(c[2]), "+f"(c[3])
        : "r"(a[0]), "r"(a[1]), "r"(a[2]), "r"(a[3]), "r"(b[0]), "r"(b[1]));
}

// ---- stage load: A [128m][32k] rows 80B; B non-trans [128n][32k] rows 80B @+20480;
//      B trans [32k][128n] rows 272B @+20480. 256 threads.
template <bool BT>
__device__ __forceinline__ void ld_chunk(const __nv_bfloat16* Ah, const __nv_bfloat16* Al, int lda,
                                         const __nv_bfloat16* Bh, const __nv_bfloat16* Bl, int ldb,
                                         uint32_t sb, int tid) {
#pragma unroll
    for (int j = 0; j < 2; j++) {
        int e = tid + j * 256;
        int r = e >> 2, seg = e & 3;
        size_t so = (size_t)r * lda + seg * 8;
        uint32_t d = sb + r * 80 + seg * 16;
        cpa16(d, Ah + so);
        cpa16(d + 10240, Al + so);
    }
    if (!BT) {
#pragma unroll
        for (int j = 0; j < 2; j++) {
            int e = tid + j * 256;
            int r = e >> 2, seg = e & 3;
            size_t so = (size_t)r * ldb + seg * 8;
            uint32_t d = sb + 20480 + r * 80 + seg * 16;
            cpa16(d, Bh + so);
            cpa16(d + 10240, Bl + so);
        }
    } else {
#pragma unroll
        for (int j = 0; j < 2; j++) {
            int e = tid + j * 256;
            int r = e >> 4, seg = e & 15;
            size_t so = (size_t)r * ldb + seg * 8;
            uint32_t d = sb + 20480 + r * 272 + seg * 16;
            cpa16(d, Bh + so);
            cpa16(d + 10240, Bl + so);
        }
    }
}

// warp tile 64x32: mt=4, nt=4. acc[4][4][4]. hi/lo sequenced for low liveness.
template <bool BT>
__device__ __forceinline__ void compute_chunk(uint32_t sb, float acc[4][4][4],
                                              int lane, int wm, int wn) {
#pragma unroll
    for (int ks = 0; ks < 2; ks++) {
        // B fragment addresses (per lane), shared by hi/lo
        uint32_t bad[2];
#pragma unroll
        for (int np = 0; np < 2; np++) {
            int g = lane >> 3, lr = lane & 7;
            if (!BT) {
                int nrow = wn * 32 + np * 16 + (g >> 1) * 8 + lr;
                bad[np] = sb + 20480 + nrow * 80 + ks * 32 + (g & 1) * 16;
            } else {
                bad[np] = sb + 20480 + (ks * 16 + (g & 1) * 8 + lr) * 272 +
                          (wn * 32 + np * 16 + (g >> 1) * 8) * 2;
            }
        }
        uint32_t aad[4];
#pragma unroll
        for (int mt = 0; mt < 4; mt++)
            aad[mt] = sb + (wm * 64 + mt * 16 + (lane & 15)) * 80 + ks * 32 + (lane >> 4) * 16;

        uint32_t af[4][4], bh[4][2], bl[4][2];
#pragma unroll
        for (int np = 0; np < 2; np++) {
            uint32_t r[4];
            if (!BT) ldm_x4(r, bad[np]); else ldm_x4t(r, bad[np]);
            bh[np * 2][0] = r[0]; bh[np * 2][1] = r[1];
            bh[np * 2 + 1][0] = r[2]; bh[np * 2 + 1][1] = r[3];
            if (!BT) ldm_x4(r, bad[np] + 10240); else ldm_x4t(r, bad[np] + 10240);
            bl[np * 2][0] = r[0]; bl[np * 2][1] = r[1];
            bl[np * 2 + 1][0] = r[2]; bl[np * 2 + 1][1] = r[3];
        }
#pragma unroll
        for (int mt = 0; mt < 4; mt++) ldm_x4(af[mt], aad[mt]);      // A-hi
#pragma unroll
        for (int mt = 0; mt < 4; mt++)
#pragma unroll
            for (int nt = 0; nt < 4; nt++) {
                mmabf(acc[mt][nt], af[mt], bh[nt]);                  // hi*hi
                mmabf(acc[mt][nt], af[mt], bl[nt]);                  // hi*lo
            }
#pragma unroll
        for (int mt = 0; mt < 4; mt++) ldm_x4(af[mt], aad[mt] + 10240);  // A-lo
#pragma unroll
        for (int mt = 0; mt < 4; mt++)
#pragma unroll
            for (int nt = 0; nt < 4; nt++)
                mmabf(acc[mt][nt], af[mt], bh[nt]);                  // lo*hi
    }
}

template <bool BT>
__device__ __forceinline__ void gemm_pipe(const __nv_bfloat16* Ah, const __nv_bfloat16* Al, int lda,
                                          const __nv_bfloat16* Bh, const __nv_bfloat16* Bl, int ldb,
                                          int n, size_t aStep, size_t bStep,
                                          uint32_t sb, float acc[4][4][4], int tid) {
    const int lane = tid & 31, wid = tid >> 5;
    const int wm = wid >> 2, wn = wid & 3;
    ld_chunk<BT>(Ah, Al, lda, Bh, Bl, ldb, sb, tid);
    cp_commit();
    for (int i = 0; i < n; i++) {
        if (i + 1 < n) {
            ld_chunk<BT>(Ah + (i + 1) * aStep, Al + (i + 1) * aStep, lda,
                         Bh + (i + 1) * bStep, Bl + (i + 1) * bStep, ldb,
                         sb + ((i + 1) & 1) * STG, tid);
            cp_commit();
            cp_wait1();
        } else {
            cp_wait0();
        }
        __syncthreads();
        compute_chunk<BT>(sb + (i & 1) * STG, acc, lane, wm, wn);
        __syncthreads();
    }
}

// ---- convert kernels ----
__global__ void convx_kernel(const float* __restrict__ x) {
    size_t i = ((size_t)blockIdx.x * 256 + threadIdx.x) * 4;
    float4 v = *(const float4*)&x[i];
    __nv_bfloat16 h0, l0, h1, l1, h2, l2, h3, l3;
    bsplit(v.x, h0, l0); bsplit(v.y, h1, l1);
    bsplit(v.z, h2, l2); bsplit(v.w, h3, l3);
    *(__nv_bfloat162*)&g_xh[i] = {h0, h1};
    *(__nv_bfloat162*)&g_xh[i + 2] = {h2, h3};
    *(__nv_bfloat162*)&g_xl[i] = {l0, l1};
    *(__nv_bfloat162*)&g_xl[i + 2] = {l2, l3};
}
__global__ void convw_kernel(const float* __restrict__ Wq, const float* __restrict__ Wk,
                             const float* __restrict__ Wv, const float* __restrict__ bq,
                             const float* __restrict__ bk, const float* __restrict__ bv) {
    int i = blockIdx.x * 256 + threadIdx.x;
    int w = i / (DD * HH), rem = i % (DD * HH);
    int r = rem / HH, c = rem % HH;
    const float* W = (w == 0) ? Wq : (w == 1) ? Wk : Wv;
    float v = W[(size_t)r * HH + c];
    __nv_bfloat16 h, l;
    bsplit(v, h, l);
    g_Wh[(size_t)r * 384 + w * 128 + c] = h;
    g_Wl[(size_t)r * 384 + w * 128 + c] = l;
    if (i < 384)
        g_bias[i] = (i < 128) ? bq[i] : (i < 256) ? bk[i - 128] : bv[i - 256];
}
__global__ void convvd_kernel() {
    int b = blockIdx.y;
    size_t i = (size_t)blockIdx.x * 256 + threadIdx.x;
    int k = (int)(i / HH);
    float inv = 1.0f / g_d[b * TT + k];
    size_t gi = (size_t)b * TT * HH + i;
    float v = g_V[gi] * inv;
    __nv_bfloat16 h, l;
    bsplit(v, h, l);
    g_Vdh[gi] = h;
    g_Vdl[gi] = l;
}

// ---- stage 1: projections ----
__global__ void __launch_bounds__(256, 2) proj_kernel() {
    extern __shared__ char sm[];
    const uint32_t sb = s2u(sm);
    const int tid = threadIdx.x, lane = tid & 31, wid = tid >> 5;
    const int wm = wid >> 2, wn = wid & 3;
    const int w = blockIdx.x, m0 = blockIdx.y * 128;
    float acc[4][4][4] = {};
    gemm_pipe<true>(g_xh + (size_t)m0 * DD, g_xl + (size_t)m0 * DD, DD,
                    g_Wh + w * 128, g_Wl + w * 128, 384,
                    32, 32, (size_t)32 * 384, sb, acc, tid);
    const float* bias = g_bias + w * 128;
#pragma unroll
    for (int mt = 0; mt < 4; mt++)
#pragma unroll
        for (int nt = 0; nt < 4; nt++)
#pragma unroll
            for (int h = 0; h < 2; h++) {
                int row = wm * 64 + mt * 16 + (lane >> 2) + h * 8;
                int col = wn * 32 + nt * 8 + (lane & 3) * 2;
                size_t gm = (size_t)(m0 + row);
                float v0 = acc[mt][nt][h * 2] + bias[col];
                float v1 = acc[mt][nt][h * 2 + 1] + bias[col + 1];
                if (w == 2) {
                    *(float2*)&g_V[gm * HH + col] = make_float2(v0, v1);
                } else {
                    __nv_bfloat16 h0, l0, h1, l1;
                    bsplit(v0, h0, l0); bsplit(v1, h1, l1);
                    __nv_bfloat162 hh = {h0, h1}, ll = {l0, l1};
                    if (w == 0) {
                        *(__nv_bfloat162*)&g_Qh[gm * HH + col] = hh;
                        *(__nv_bfloat162*)&g_Ql[gm * HH + col] = ll;
                    } else {
                        *(__nv_bfloat162*)&g_Kh[gm * HH + col] = hh;
                        *(__nv_bfloat162*)&g_Kl[gm * HH + col] = ll;
                    }
                }
            }
}

// ---- stage 2: scores ----
__global__ void __launch_bounds__(256, 2) scores_kernel() {
    const int kT = blockIdx.x, qT = blockIdx.y, b = blockIdx.z;
    if (kT < qT) return;
    extern __shared__ char sm[];
    const uint32_t sb = s2u(sm);
    const int tid = threadIdx.x, lane = tid & 31, wid = tid >> 5;
    const int wm = wid >> 2, wn = wid & 3;
    const int q0 = qT * 128, k0 = kT * 128;
    const size_t mq = (size_t)b * TT + q0, mk = (size_t)b * TT + k0;
    float acc[4][4][4] = {};
    gemm_pipe<false>(g_Qh + mq * HH, g_Ql + mq * HH, HH,
                     g_Kh + mk * HH, g_Kl + mk * HH, HH,
                     4, 32, 32, sb, acc, tid);
    float* se = (float*)sm;  // [128][136]
#pragma unroll
    for (int mt = 0; mt < 4; mt++)
#pragma unroll
        for (int nt = 0; nt < 4; nt++)
#pragma unroll
            for (int h = 0; h < 2; h++) {
                int row = wm * 64 + mt * 16 + (lane >> 2) + h * 8;
                int col = wn * 32 + nt * 8 + (lane & 3) * 2;
                int q = q0 + row;
                float e0 = (q <= k0 + col) ? __expf(acc[mt][nt][h * 2]) : 0.f;
                float e1 = (q <= k0 + col + 1) ? __expf(acc[mt][nt][h * 2 + 1]) : 0.f;
                se[row * 136 + col] = e0;
                se[row * 136 + col + 1] = e1;
            }
    __syncthreads();
    if (tid < 128) {
        float s = 0.f;
#pragma unroll 8
        for (int r = 0; r < 128; r++) s += se[r * 136 + tid];
        atomicAdd(&g_d[b * TT + k0 + tid], s);
    }
    __nv_bfloat16* Eh = g_Eh + (size_t)b * TT * TT;
    __nv_bfloat16* El = g_El + (size_t)b * TT * TT;
#pragma unroll 4
    for (int i = 0; i < 32; i++) {
        int e = tid + i * 256;
        int q = e >> 6, kk = (e & 63) * 2;
        float v0 = se[q * 136 + kk], v1 = se[q * 136 + kk + 1];
        __nv_bfloat16 h0, l0, h1, l1;
        bsplit(v0, h0, l0); bsplit(v1, h1, l1);
        size_t o = (size_t)(q0 + q) * TT + k0 + kk;
        *(__nv_bfloat162*)&Eh[o] = {h0, h1};
        *(__nv_bfloat162*)&El[o] = {l0, l1};
    }
}

// ---- stage 3: out ----
__global__ void __launch_bounds__(256, 2) out_kernel(float* __restrict__ Out) {
    const int seg = blockIdx.x, qT = blockIdx.y, b = blockIdx.z;
    extern __shared__ char sm[];
    const uint32_t sb = s2u(sm);
    const int tid = threadIdx.x, lane = tid & 31, wid = tid >> 5;
    const int wm = wid >> 2, wn = wid & 3;
    const int q0 = qT * 128;
    const int c0 = q0 / 32 + seg;
    const int nch = (TT - q0) / 32;
    const int nIter = (nch - seg + 3) / 4;
    if (nIter <= 0) return;
    const __nv_bfloat16* Ah = g_Eh + ((size_t)b * TT + q0) * TT + (size_t)c0 * 32;
    const __nv_bfloat16* Al = g_El + ((size_t)b * TT + q0) * TT + (size_t)c0 * 32;
    const __nv_bfloat16* Bh = g_Vdh + (size_t)b * TT * HH + (size_t)c0 * 32 * HH;
    const __nv_bfloat16* Bl = g_Vdl + (size_t)b * TT * HH + (size_t)c0 * 32 * HH;
    float acc[4][4][4] = {};
    gemm_pipe<true>(Ah, Al, TT, Bh, Bl, HH, nIter, 128, (size_t)128 * HH, sb, acc, tid);
    float* ob = Out + ((size_t)b * TT + q0) * HH;
#pragma unroll
    for (int mt = 0; mt < 4; mt++)
#pragma unroll
        for (int nt = 0; nt < 4; nt++)
#pragma unroll
            for (int h = 0; h < 2; h++) {
                int row = wm * 64 + mt * 16 + (lane >> 2) + h * 8;
                int col = wn * 32 + nt * 8 + (lane & 3) * 2;
                atomicAdd(&ob[(size_t)row * HH + col], acc[mt][nt][h * 2]);
                atomicAdd(&ob[(size_t)row * HH + col + 1], acc[mt][nt][h * 2 + 1]);
            }
}

// ----------------------------------------------------------------------------
extern "C" void kernel_launch(void* const* d_in, const int* in_sizes, int n_in,
                              void* d_out, int out_size) {
    const float* x  = (const float*)d_in[0];
    const float* Wq = (const float*)d_in[1];
    const float* bq = (const float*)d_in[2];
    const float* Wk = (const float*)d_in[3];
    const float* bk = (const float*)d_in[4];
    const float* Wv = (const float*)d_in[5];
    const float* bv = (const float*)d_in[6];
    float* out = (float*)d_out;

    float* pd;
    cudaGetSymbolAddress((void**)&pd, g_d);
    cudaMemsetAsync(pd, 0, BB * TT * sizeof(float));
    cudaMemsetAsync(out, 0, (size_t)out_size * sizeof(float));

    cudaFuncSetAttribute(proj_kernel, cudaFuncAttributeMaxDynamicSharedMemorySize, SMEM_BYTES);
    cudaFuncSetAttribute(scores_kernel, cudaFuncAttributeMaxDynamicSharedMemorySize, SMEM_BYTES);
    cudaFuncSetAttribute(out_kernel, cudaFuncAttributeMaxDynamicSharedMemorySize, SMEM_BYTES);

    convx_kernel<<<BB * TT * DD / 1024, 256>>>(x);
    convw_kernel<<<3 * DD * HH / 256, 256>>>(Wq, Wk, Wv, bq, bk, bv);
    proj_kernel<<<dim3(3, BB * TT / 128), 256, SMEM_BYTES>>>();
    scores_kernel<<<dim3(16, 16, BB), 256, SMEM_BYTES>>>();
    convvd_kernel<<<dim3(TT * HH / 256, BB), 256>>>();
    out_kernel<<<dim3(4, 16, BB), 256, SMEM_BYTES>>>(out);
}